// round 6
// baseline (speedup 1.0000x reference)
#include <cuda_runtime.h>
#include <cstdint>

typedef unsigned long long u64;

// ---------------- problem constants (fixed by setup_inputs) ----------------
#define S_TOK 3120          // F*H*W = 2*30*52
#define DIM_  1536
#define NH    12
#define HD    128
#define KV    5632          // attention window length (== MAX_ATTN exactly)
#define NKT   88            // KV / 64
#define NEW0  2512          // offset of new tokens inside window (7800-5288)
#define WIN0  5288          // window start in cache
#define SD    (S_TOK*DIM_)              // 4,792,320
#define KVD   ((size_t)NH*KV*HD)        // 8,650,752

// scratch: yq | yk | yv | Qh(head-major) | Oattn(token-major) | Kw | Vw
__device__ float g_scratch[5*(size_t)SD + 2*KVD];

// ---------------- packed f32x2 helpers (Blackwell FFMA2 path) ----------------
__device__ __forceinline__ u64 bc2(float a) {
    u64 r; asm("mov.b64 %0, {%1, %1};" : "=l"(r) : "f"(a)); return r;
}
__device__ __forceinline__ void fma2(u64 &c, u64 a, u64 b) {
    asm("fma.rn.f32x2 %0, %1, %2, %0;" : "+l"(c) : "l"(a), "l"(b));
}
__device__ __forceinline__ void mul2(u64 &c, u64 a) {
    asm("mul.rn.f32x2 %0, %0, %1;" : "+l"(c) : "l"(a));
}
__device__ __forceinline__ float2 up2(u64 v) {
    float lo, hi; asm("mov.b64 {%0, %1}, %2;" : "=f"(lo), "=f"(hi) : "l"(v));
    return make_float2(lo, hi);
}

// ============================================================================
// SGEMM (NT): C[m,n] = sum_k A[m,k]*W[n,k] + bias[n].  N=K=1536 fixed.
// 128x128x16 tile, 256 threads, 8x8 per thread, packed FMA2.
// ============================================================================
__global__ void __launch_bounds__(256) sgemm_nt(
    const float* __restrict__ A, const float* __restrict__ W,
    const float* __restrict__ bias, float* __restrict__ C, int M)
{
    __shared__ __align__(16) float As[16][128];
    __shared__ __align__(16) float Ws[16][128];
    const int tid = threadIdx.x;
    const int m0 = blockIdx.y * 128;
    const int n0 = blockIdx.x * 128;
    const int ty = tid >> 4, tx = tid & 15;
    const int lr = tid >> 2;             // 0..63
    const int lk = (tid & 3) << 2;       // 0,4,8,12
    const bool am0 = (m0 + lr)      < M;
    const bool am1 = (m0 + lr + 64) < M;
    const float* Ap0 = A + (size_t)(m0 + lr) * DIM_ + lk;
    const float* Ap1 = Ap0 + (size_t)64 * DIM_;
    const float* Wp0 = W + (size_t)(n0 + lr) * DIM_ + lk;
    const float* Wp1 = Wp0 + (size_t)64 * DIM_;

    u64 acc[8][4];
#pragma unroll
    for (int i = 0; i < 8; ++i)
#pragma unroll
        for (int j = 0; j < 4; ++j) acc[i][j] = 0ull;

    float4 z4 = make_float4(0.f, 0.f, 0.f, 0.f);
    float4 pa0 = am0 ? *(const float4*)Ap0 : z4;
    float4 pa1 = am1 ? *(const float4*)Ap1 : z4;
    float4 pw0 = *(const float4*)Wp0;
    float4 pw1 = *(const float4*)Wp1;

    for (int kt = 0; kt < 96; ++kt) {
        __syncthreads();
        As[lk+0][lr]    = pa0.x; As[lk+1][lr]    = pa0.y;
        As[lk+2][lr]    = pa0.z; As[lk+3][lr]    = pa0.w;
        As[lk+0][lr+64] = pa1.x; As[lk+1][lr+64] = pa1.y;
        As[lk+2][lr+64] = pa1.z; As[lk+3][lr+64] = pa1.w;
        Ws[lk+0][lr]    = pw0.x; Ws[lk+1][lr]    = pw0.y;
        Ws[lk+2][lr]    = pw0.z; Ws[lk+3][lr]    = pw0.w;
        Ws[lk+0][lr+64] = pw1.x; Ws[lk+1][lr+64] = pw1.y;
        Ws[lk+2][lr+64] = pw1.z; Ws[lk+3][lr+64] = pw1.w;
        __syncthreads();

        if (kt < 95) {
            int ko = (kt + 1) * 16;
            pa0 = am0 ? *(const float4*)(Ap0 + ko) : z4;
            pa1 = am1 ? *(const float4*)(Ap1 + ko) : z4;
            pw0 = *(const float4*)(Wp0 + ko);
            pw1 = *(const float4*)(Wp1 + ko);
        }

#pragma unroll
        for (int kk = 0; kk < 16; ++kk) {
            float4 a0 = *(const float4*)&As[kk][ty << 2];
            float4 a1 = *(const float4*)&As[kk][64 + (ty << 2)];
            ulonglong2 w0 = *(const ulonglong2*)&Ws[kk][tx << 2];
            ulonglong2 w1 = *(const ulonglong2*)&Ws[kk][64 + (tx << 2)];
            u64 b0 = bc2(a0.x), b1 = bc2(a0.y), b2 = bc2(a0.z), b3 = bc2(a0.w);
            u64 b4 = bc2(a1.x), b5 = bc2(a1.y), b6 = bc2(a1.z), b7 = bc2(a1.w);
            u64 bb[8] = {b0,b1,b2,b3,b4,b5,b6,b7};
#pragma unroll
            for (int i = 0; i < 8; ++i) {
                fma2(acc[i][0], bb[i], w0.x);
                fma2(acc[i][1], bb[i], w0.y);
                fma2(acc[i][2], bb[i], w1.x);
                fma2(acc[i][3], bb[i], w1.y);
            }
        }
    }

    float4 bv0 = *(const float4*)&bias[n0 + (tx << 2)];
    float4 bv1 = *(const float4*)&bias[n0 + 64 + (tx << 2)];
#pragma unroll
    for (int i = 0; i < 8; ++i) {
        int r = (i < 4) ? ((ty << 2) + i) : (64 + (ty << 2) + (i - 4));
        int mg = m0 + r;
        if (mg >= M) continue;
        float2 p0 = up2(acc[i][0]), p1 = up2(acc[i][1]);
        float2 p2 = up2(acc[i][2]), p3 = up2(acc[i][3]);
        float4 o0 = make_float4(p0.x + bv0.x, p0.y + bv0.y, p1.x + bv0.z, p1.y + bv0.w);
        float4 o1 = make_float4(p2.x + bv1.x, p2.y + bv1.y, p3.x + bv1.z, p3.y + bv1.w);
        *(float4*)&C[(size_t)mg * DIM_ + n0 + (tx << 2)]      = o0;
        *(float4*)&C[(size_t)mg * DIM_ + n0 + 64 + (tx << 2)] = o1;
    }
}

// ============================================================================
// Cache window copy: window tokens [0, NEW0) from cache, into head-major K/V
// cache layout (1,15600,12,128) flat: token*1536 + e
// ============================================================================
__global__ void cache_copy_kernel(const float* __restrict__ ck, const float* __restrict__ cv,
                                  float* __restrict__ Kw, float* __restrict__ Vw)
{
    int t = blockIdx.x;                 // 0..2511
    int e = threadIdx.x << 2;           // 384 threads * 4 = 1536
    int n = e >> 7, d = e & 127;
    *(float4*)&Kw[((size_t)n * KV + t) * HD + d] = *(const float4*)&ck[(size_t)(WIN0 + t) * DIM_ + e];
    *(float4*)&Vw[((size_t)n * KV + t) * HD + d] = *(const float4*)&cv[(size_t)(WIN0 + t) * DIM_ + e];
}

// ============================================================================
// RMSNorm(1536) + RoPE + scatter: Qh (head-major), K window, V window
// ============================================================================
__global__ void __launch_bounds__(256) norm_rope_kernel(
    const float* __restrict__ yq, const float* __restrict__ yk, const float* __restrict__ yv,
    const float* __restrict__ theta, const float* __restrict__ gq, const float* __restrict__ gk,
    float* __restrict__ Qh, float* __restrict__ Kw, float* __restrict__ Vw)
{
    const int s = blockIdx.x;
    const int tid = threadIdx.x;
    __shared__ float cs[64], sn[64];
    __shared__ float redq[8], redk[8];

    const int f   = s / 1560;           // frame_seqlen = 30*52
    const int rem = s % 1560;
    const int h   = rem / 52;
    const int w   = rem % 52;

    if (tid < 64) {
        int j = tid;
        // ct=22, ch=21: [0,22)->frame axis (start_frame=5), [22,43)->h, [43,64)->w
        int row = (j < 22) ? (5 + f) : ((j < 43) ? h : w);
        float ang = theta[row * 64 + j];
        float sv, cv; sincosf(ang, &sv, &cv);
        cs[j] = cv; sn[j] = sv;
    }

    const float* q = yq + (size_t)s * DIM_;
    const float* k = yk + (size_t)s * DIM_;
    const float* v = yv + (size_t)s * DIM_;

    float sq = 0.f, sk = 0.f;
    for (int e = tid; e < DIM_; e += 256) {
        float a = q[e]; sq += a * a;
        float b = k[e]; sk += b * b;
    }
#pragma unroll
    for (int off = 16; off; off >>= 1) {
        sq += __shfl_xor_sync(0xffffffffu, sq, off);
        sk += __shfl_xor_sync(0xffffffffu, sk, off);
    }
    if ((tid & 31) == 0) { redq[tid >> 5] = sq; redk[tid >> 5] = sk; }
    __syncthreads();
    float tq = 0.f, tk = 0.f;
#pragma unroll
    for (int i = 0; i < 8; ++i) { tq += redq[i]; tk += redk[i]; }
    const float rq = rsqrtf(tq * (1.f / 1536.f) + 1e-6f);
    const float rk = rsqrtf(tk * (1.f / 1536.f) + 1e-6f);

    // 768 rope pairs; pair p -> head n=p>>6, half-dim j=p&63, elements (2p, 2p+1)
    for (int p = tid; p < 768; p += 256) {
        int n = p >> 6, j = p & 63;
        float c = cs[j], si = sn[j];
        int e = p << 1;
        float xr = q[e]     * rq * gq[e];
        float xi = q[e + 1] * rq * gq[e + 1];
        float* qo = Qh + ((size_t)n * S_TOK + s) * HD + (j << 1);
        qo[0] = xr * c - xi * si;
        qo[1] = xr * si + xi * c;
        float kr = k[e]     * rk * gk[e];
        float ki = k[e + 1] * rk * gk[e + 1];
        float* ko = Kw + ((size_t)n * KV + NEW0 + s) * HD + (j << 1);
        ko[0] = kr * c - ki * si;
        ko[1] = kr * si + ki * c;
    }
    for (int e = tid; e < DIM_; e += 256) {
        int n = e >> 7, d = e & 127;
        Vw[((size_t)n * KV + NEW0 + s) * HD + d] = v[e];
    }
}

// ============================================================================
// Flash attention, fp32 FFMA2. Block = (64-query tile, head). 256 threads.
// smem (dynamic, 114688B): QT[128][64] swz | KT[128][64] swz | V[64][128] | PT[64][64] swz
// XOR swizzle: value (d, r) stored at d*64 + ((r>>2)^((d>>2)&15))*4 + (r&3)
// ============================================================================
#define ATTN_SMEM ((8192 + 8192 + 8192 + 4096) * 4)

__global__ void __launch_bounds__(256) attn_kernel(
    const float* __restrict__ Qh, const float* __restrict__ Kw,
    const float* __restrict__ Vw, float* __restrict__ O)
{
    extern __shared__ __align__(16) float sm[];
    float* Qs = sm;                 // 8192 floats
    float* Ks = sm + 8192;          // 8192
    float* Vs = sm + 16384;         // 8192
    float* Ps = sm + 24576;         // 4096

    const int tid  = threadIdx.x;
    const int head = blockIdx.y;
    const int m0   = blockIdx.x * 64;
    const int ty   = tid >> 4, tx = tid & 15;
    const float scale = 0.08838834764831845f;  // 1/sqrt(128)

    // ---- fill Q^T swizzled, scale folded in ----
#pragma unroll
    for (int p = 0; p < 8; ++p) {
        int fidx = tid + p * 256;
        int r  = fidx >> 5;            // 0..63
        int dq = (fidx & 31) << 2;     // 0..124
        float4 v = make_float4(0.f, 0.f, 0.f, 0.f);
        int sg = m0 + r;
        if (sg < S_TOK) v = *(const float4*)&Qh[((size_t)head * S_TOK + sg) * HD + dq];
        int co = (((r >> 2) ^ ((dq >> 2) & 15)) << 2) + (r & 3);
        Qs[(dq + 0) * 64 + co] = v.x * scale;
        Qs[(dq + 1) * 64 + co] = v.y * scale;
        Qs[(dq + 2) * 64 + co] = v.z * scale;
        Qs[(dq + 3) * 64 + co] = v.w * scale;
    }

    u64 o2[4][4];
#pragma unroll
    for (int i = 0; i < 4; ++i)
#pragma unroll
        for (int j = 0; j < 4; ++j) o2[i][j] = 0ull;
    float mrow[4] = {-1e30f, -1e30f, -1e30f, -1e30f};
    float lrow[4] = {0.f, 0.f, 0.f, 0.f};

    for (int kt = 0; kt < NKT; ++kt) {
        const int t0 = kt * 64;
        __syncthreads();
        // ---- fill K^T (swizzled) + V (natural) ----
#pragma unroll
        for (int p = 0; p < 8; ++p) {
            int fidx = tid + p * 256;
            int c  = fidx >> 5;
            int dd = (fidx & 31) << 2;
            const float4 kvv = *(const float4*)&Kw[((size_t)head * KV + t0 + c) * HD + dd];
            int co = (((c >> 2) ^ ((dd >> 2) & 15)) << 2) + (c & 3);
            Ks[(dd + 0) * 64 + co] = kvv.x;
            Ks[(dd + 1) * 64 + co] = kvv.y;
            Ks[(dd + 2) * 64 + co] = kvv.z;
            Ks[(dd + 3) * 64 + co] = kvv.w;
            *(float4*)&Vs[c * HD + dd] = *(const float4*)&Vw[((size_t)head * KV + t0 + c) * HD + dd];
        }
        __syncthreads();

        // ---- phase 1: S = Q K^T (thread -> rows ty*4.., cols tx*4..) ----
        u64 s2[4][2];
#pragma unroll
        for (int i = 0; i < 4; ++i) { s2[i][0] = 0ull; s2[i][1] = 0ull; }
#pragma unroll 8
        for (int kk = 0; kk < 128; ++kk) {
            int g = (kk >> 2) & 15;
            float4 a = *(const float4*)&Qs[kk * 64 + ((ty ^ g) << 2)];
            ulonglong2 w = *(const ulonglong2*)&Ks[kk * 64 + ((tx ^ g) << 2)];
            u64 b0 = bc2(a.x), b1 = bc2(a.y), b2 = bc2(a.z), b3 = bc2(a.w);
            fma2(s2[0][0], b0, w.x); fma2(s2[0][1], b0, w.y);
            fma2(s2[1][0], b1, w.x); fma2(s2[1][1], b1, w.y);
            fma2(s2[2][0], b2, w.x); fma2(s2[2][1], b2, w.y);
            fma2(s2[3][0], b3, w.x); fma2(s2[3][1], b3, w.y);
        }

        // ---- online softmax: rows shared by the 16 lanes with same ty ----
        float sc[4][4];
#pragma unroll
        for (int rr = 0; rr < 4; ++rr) {
            float2 a = up2(s2[rr][0]), b = up2(s2[rr][1]);
            sc[rr][0] = a.x; sc[rr][1] = a.y; sc[rr][2] = b.x; sc[rr][3] = b.y;
        }
#pragma unroll
        for (int rr = 0; rr < 4; ++rr) {
            float m = fmaxf(fmaxf(sc[rr][0], sc[rr][1]), fmaxf(sc[rr][2], sc[rr][3]));
#pragma unroll
            for (int off = 1; off < 16; off <<= 1)
                m = fmaxf(m, __shfl_xor_sync(0xffffffffu, m, off));
            float mn = fmaxf(mrow[rr], m);
            float alpha = __expf(mrow[rr] - mn);
            mrow[rr] = mn;
            float rs = 0.f;
#pragma unroll
            for (int j = 0; j < 4; ++j) {
                float pv = __expf(sc[rr][j] - mn);
                sc[rr][j] = pv; rs += pv;
            }
#pragma unroll
            for (int off = 1; off < 16; off <<= 1)
                rs += __shfl_xor_sync(0xffffffffu, rs, off);
            lrow[rr] = lrow[rr] * alpha + rs;
            u64 a2 = bc2(alpha);
#pragma unroll
            for (int j = 0; j < 4; ++j) mul2(o2[rr][j], a2);
        }

        // ---- write P^T swizzled: P[q=ty*4+rr][k=tx*4+jj] at co=((ty^tx)<<2)+rr ----
#pragma unroll
        for (int jj = 0; jj < 4; ++jj)
#pragma unroll
            for (int rr = 0; rr < 4; ++rr)
                Ps[((tx << 2) + jj) * 64 + ((ty ^ tx) << 2) + rr] = sc[rr][jj];
        __syncthreads();

        // ---- phase 2: O += P^T V (thread -> rows ty*4.., cols tx*4 and 64+tx*4) ----
#pragma unroll 4
        for (int kk = 0; kk < 64; ++kk) {
            int gk = (kk >> 2) & 15;
            float4 pv = *(const float4*)&Ps[kk * 64 + ((ty ^ gk) << 2)];
            ulonglong2 v0 = *(const ulonglong2*)&Vs[kk * HD + (tx << 2)];
            ulonglong2 v1 = *(const ulonglong2*)&Vs[kk * HD + 64 + (tx << 2)];
            u64 b0 = bc2(pv.x), b1 = bc2(pv.y), b2 = bc2(pv.z), b3 = bc2(pv.w);
            fma2(o2[0][0], b0, v0.x); fma2(o2[0][1], b0, v0.y);
            fma2(o2[0][2], b0, v1.x); fma2(o2[0][3], b0, v1.y);
            fma2(o2[1][0], b1, v0.x); fma2(o2[1][1], b1, v0.y);
            fma2(o2[1][2], b1, v1.x); fma2(o2[1][3], b1, v1.y);
            fma2(o2[2][0], b2, v0.x); fma2(o2[2][1], b2, v0.y);
            fma2(o2[2][2], b2, v1.x); fma2(o2[2][3], b2, v1.y);
            fma2(o2[3][0], b3, v0.x); fma2(o2[3][1], b3, v0.y);
            fma2(o2[3][2], b3, v1.x); fma2(o2[3][3], b3, v1.y);
        }
    }

    // ---- epilogue: O[q][:] /= l, write token-major (s, head*128+d) ----
#pragma unroll
    for (int rr = 0; rr < 4; ++rr) {
        int q = m0 + (ty << 2) + rr;
        if (q >= S_TOK) continue;
        float inv = 1.f / lrow[rr];
        float2 p0 = up2(o2[rr][0]), p1 = up2(o2[rr][1]);
        float2 p2 = up2(o2[rr][2]), p3 = up2(o2[rr][3]);
        float4 w0 = make_float4(p0.x * inv, p0.y * inv, p1.x * inv, p1.y * inv);
        float4 w1 = make_float4(p2.x * inv, p2.y * inv, p3.x * inv, p3.y * inv);
        float* base = O + (size_t)q * DIM_ + head * HD;
        *(float4*)&base[(tx << 2)]      = w0;
        *(float4*)&base[64 + (tx << 2)] = w1;
    }
}

// ============================================================================
extern "C" void kernel_launch(void* const* d_in, const int* in_sizes, int n_in,
                              void* d_out, int out_size)
{
    const float* x     = (const float*)d_in[0];
    const float* theta = (const float*)d_in[1];
    const float* ck    = (const float*)d_in[2];
    const float* cv    = (const float*)d_in[3];
    const float* wq    = (const float*)d_in[4];
    const float* bq    = (const float*)d_in[5];
    const float* wk    = (const float*)d_in[6];
    const float* bk    = (const float*)d_in[7];
    const float* wv    = (const float*)d_in[8];
    const float* bv    = (const float*)d_in[9];
    const float* wo    = (const float*)d_in[10];
    const float* bo    = (const float*)d_in[11];
    const float* gq    = (const float*)d_in[12];
    const float* gk    = (const float*)d_in[13];
    float* out = (float*)d_out;

    float* scr = nullptr;
    cudaGetSymbolAddress((void**)&scr, g_scratch);
    float* yq  = scr;
    float* yk  = scr + (size_t)SD;
    float* yv  = scr + 2 * (size_t)SD;
    float* Qh  = scr + 3 * (size_t)SD;
    float* Oat = scr + 4 * (size_t)SD;
    float* Kw  = scr + 5 * (size_t)SD;
    float* Vw  = Kw + KVD;

    cudaFuncSetAttribute(attn_kernel, cudaFuncAttributeMaxDynamicSharedMemorySize, ATTN_SMEM);

    dim3 gg(12, 25);   // N=1536/128, M=ceil(3120/128)
    sgemm_nt<<<gg, 256>>>(x, wq, bq, yq, S_TOK);
    sgemm_nt<<<gg, 256>>>(x, wk, bk, yk, S_TOK);
    sgemm_nt<<<gg, 256>>>(x, wv, bv, yv, S_TOK);
    cache_copy_kernel<<<NEW0, 384>>>(ck, cv, Kw, Vw);
    norm_rope_kernel<<<S_TOK, 256>>>(yq, yk, yv, theta, gq, gk, Qh, Kw, Vw);
    attn_kernel<<<dim3(49, NH), 256, ATTN_SMEM>>>(Qh, Kw, Vw, Oat);
    sgemm_nt<<<gg, 256>>>(Oat, wo, bo, out, S_TOK);
}

// round 10
// speedup vs baseline: 1.2176x; 1.2176x over previous
#include <cuda_runtime.h>
#include <cuda_bf16.h>
#include <cstdint>

typedef unsigned long long u64;

// ---------------- problem constants (fixed by setup_inputs) ----------------
#define S_TOK 3120          // F*H*W = 2*30*52
#define DIM_  1536
#define NH    12
#define HD    128
#define KV    5632          // attention window length (== MAX_ATTN exactly)
#define NKT   88            // KV / 64
#define NEW0  2512          // offset of new tokens inside window (7800-5288)
#define WIN0  5288          // window start in cache
#define SD    (S_TOK*DIM_)              // 4,792,320
#define KVD   ((size_t)NH*KV*HD)        // 8,650,752
#define WSZ   (DIM_*DIM_)               // 2,359,296

// fp32 scratch: yq | yk | yv | Qh(head-major) | Oattn(token-major) | Kw | Vw
__device__ float g_scratch[5*(size_t)SD + 2*KVD];
// split-bf16 scratch
__device__ __align__(16) __nv_bfloat16 g_xhi[SD], g_xlo[SD];
__device__ __align__(16) __nv_bfloat16 g_whi[4*(size_t)WSZ], g_wlo[4*(size_t)WSZ];
__device__ __align__(16) __nv_bfloat16 g_ohi[SD], g_olo[SD];

// ---------------- packed f32x2 helpers (Blackwell FFMA2 path) ----------------
__device__ __forceinline__ u64 bc2(float a) {
    u64 r; asm("mov.b64 %0, {%1, %1};" : "=l"(r) : "f"(a)); return r;
}
__device__ __forceinline__ void fma2(u64 &c, u64 a, u64 b) {
    asm("fma.rn.f32x2 %0, %1, %2, %0;" : "+l"(c) : "l"(a), "l"(b));
}
__device__ __forceinline__ void mul2(u64 &c, u64 a) {
    asm("mul.rn.f32x2 %0, %0, %1;" : "+l"(c) : "l"(a));
}
__device__ __forceinline__ float2 up2(u64 v) {
    float lo, hi; asm("mov.b64 {%0, %1}, %2;" : "=f"(lo), "=f"(hi) : "l"(v));
    return make_float2(lo, hi);
}

// ---------------- mma.sync / ldmatrix / cp.async helpers (NOT a-gated) ------
__device__ __forceinline__ uint32_t smem_u32(const void* p) {
    uint32_t a; asm("{ .reg .u64 t; cvta.to.shared.u64 t, %1; cvt.u32.u64 %0, t; }" : "=r"(a) : "l"(p));
    return a;
}
__device__ __forceinline__ void ldsm4(uint32_t* r, uint32_t a) {
    asm volatile("ldmatrix.sync.aligned.m8n8.x4.shared.b16 {%0,%1,%2,%3}, [%4];"
                 : "=r"(r[0]), "=r"(r[1]), "=r"(r[2]), "=r"(r[3]) : "r"(a));
}
__device__ __forceinline__ void mma16816(float* c, const uint32_t* a, uint32_t b0, uint32_t b1) {
    asm volatile("mma.sync.aligned.m16n8k16.row.col.f32.bf16.bf16.f32 "
                 "{%0,%1,%2,%3}, {%4,%5,%6,%7}, {%8,%9}, {%0,%1,%2,%3};"
                 : "+f"(c[0]), "+f"(c[1]), "+f"(c[2]), "+f"(c[3])
                 : "r"(a[0]), "r"(a[1]), "r"(a[2]), "r"(a[3]), "r"(b0), "r"(b1));
}
__device__ __forceinline__ void cp16(uint32_t d, const void* s) {
    asm volatile("cp.async.cg.shared.global [%0], [%1], 16;" :: "r"(d), "l"(s));
}
__device__ __forceinline__ void cp16z(uint32_t d, const void* s, int sz) {
    asm volatile("cp.async.cg.shared.global [%0], [%1], 16, %2;" :: "r"(d), "l"(s), "r"(sz));
}
__device__ __forceinline__ void cp_commit() {
    asm volatile("cp.async.commit_group;" ::: "memory");
}
template<int N> __device__ __forceinline__ void cp_wait() {
    asm volatile("cp.async.wait_group %0;" :: "n"(N) : "memory");
}
__device__ __forceinline__ uint32_t sw128(uint32_t off) { return off ^ ((off >> 3) & 0x70); }

// ============================================================================
// split fp32 -> (hi, lo) bf16 pair. n4 = elems/4.
// ============================================================================
__global__ void __launch_bounds__(256) split_kernel(
    const float* __restrict__ src, __nv_bfloat16* __restrict__ hi,
    __nv_bfloat16* __restrict__ lo, int n4)
{
    int i = blockIdx.x * 256 + threadIdx.x;
    if (i >= n4) return;
    float4 v = ((const float4*)src)[i];
    __nv_bfloat16 h0 = __float2bfloat16(v.x), h1 = __float2bfloat16(v.y);
    __nv_bfloat16 h2 = __float2bfloat16(v.z), h3 = __float2bfloat16(v.w);
    __nv_bfloat16 l0 = __float2bfloat16(v.x - __bfloat162float(h0));
    __nv_bfloat16 l1 = __float2bfloat16(v.y - __bfloat162float(h1));
    __nv_bfloat16 l2 = __float2bfloat16(v.z - __bfloat162float(h2));
    __nv_bfloat16 l3 = __float2bfloat16(v.w - __bfloat162float(h3));
    union { __nv_bfloat162 b[2]; uint2 u; } H, L;
    H.b[0] = __nv_bfloat162(h0, h1); H.b[1] = __nv_bfloat162(h2, h3);
    L.b[0] = __nv_bfloat162(l0, l1); L.b[1] = __nv_bfloat162(l2, l3);
    ((uint2*)hi)[i] = H.u;
    ((uint2*)lo)[i] = L.u;
}

// ============================================================================
// Split-bf16 GEMM (NT) via mma.sync.m16n8k16: C = A*W^T + bias
//   D = AhWh + AhWl + AlWh (fp32 accum). Tile 128x128x64, 256 thr, 8 warps.
//   smem/stage: Ah|Al|Wh|Wl, each 128x64 bf16 (16KB) SW128-swizzled. 2 stages.
// ============================================================================
#define T_AH 0
#define T_AL 16384
#define T_WH 32768
#define T_WL 49152
#define STAGE_B 65536
#define GEMM_SMEM (2*STAGE_B)

__global__ void __launch_bounds__(256) gemm_mma(
    const __nv_bfloat16* __restrict__ Ah, const __nv_bfloat16* __restrict__ Al,
    const __nv_bfloat16* __restrict__ Wh, const __nv_bfloat16* __restrict__ Wl,
    const float* __restrict__ bias, float* __restrict__ C, int M)
{
    extern __shared__ __align__(16) char smem[];
    const uint32_t sb = smem_u32(smem);
    const int tid  = threadIdx.x;
    const int lane = tid & 31;
    const int warp = tid >> 5;
    const int m0 = blockIdx.y * 128, n0 = blockIdx.x * 128;
    const int wm = (warp >> 2) * 64;       // 0 or 64
    const int wn = (warp & 3) * 32;        // 0,32,64,96

    // per-thread load slots: 4 iters, idx = tid + i*256; row = idx>>3, chunk = idx&7
    const int lrow = tid >> 3;             // + 32*i
    const int lch  = tid & 7;

    float acc[4][4][4];
#pragma unroll
    for (int mi = 0; mi < 4; ++mi)
#pragma unroll
        for (int ni = 0; ni < 4; ++ni)
#pragma unroll
            for (int j = 0; j < 4; ++j) acc[mi][ni][j] = 0.f;

    // ---- stage loader (cp.async) ----
    auto load_stage = [&](int c, int buf) {
        const uint32_t db = sb + buf * STAGE_B;
        const int kc = c * 64 + lch * 8;   // bf16 element column
#pragma unroll
        for (int i = 0; i < 4; ++i) {
            const int row = lrow + 32 * i;
            const uint32_t so = sw128((uint32_t)(row * 128 + lch * 16));
            const int mg = m0 + row;
            const int sz = (mg < M) ? 16 : 0;
            const size_t ao = (size_t)mg * DIM_ + kc;
            cp16z(db + T_AH + so, Ah + ao, sz);
            cp16z(db + T_AL + so, Al + ao, sz);
            const size_t wo = (size_t)(n0 + row) * DIM_ + kc;
            cp16(db + T_WH + so, Wh + wo);
            cp16(db + T_WL + so, Wl + wo);
        }
    };

    load_stage(0, 0);
    cp_commit();

    for (int c = 0; c < 24; ++c) {
        if (c < 23) { load_stage(c + 1, (c + 1) & 1); cp_commit(); }
        if (c < 23) cp_wait<1>(); else cp_wait<0>();
        __syncthreads();

        const uint32_t base = sb + (c & 1) * STAGE_B;
        const int rA = wm + (lane & 15);
        const int rW = wn + (lane & 15);
#pragma unroll
        for (int ks = 0; ks < 4; ++ks) {
            const int kb = ks * 32 + ((lane >> 4) << 4);
            uint32_t ah[4][4], al[4][4], wh[2][4], wl[2][4];
#pragma unroll
            for (int mi = 0; mi < 4; ++mi) {
                ldsm4(ah[mi], base + T_AH + sw128((uint32_t)((rA + mi * 16) * 128 + kb)));
                ldsm4(al[mi], base + T_AL + sw128((uint32_t)((rA + mi * 16) * 128 + kb)));
            }
#pragma unroll
            for (int nj = 0; nj < 2; ++nj) {
                ldsm4(wh[nj], base + T_WH + sw128((uint32_t)((rW + nj * 16) * 128 + kb)));
                ldsm4(wl[nj], base + T_WL + sw128((uint32_t)((rW + nj * 16) * 128 + kb)));
            }
#pragma unroll
            for (int mi = 0; mi < 4; ++mi)
#pragma unroll
                for (int ni = 0; ni < 4; ++ni) {
                    const int nj = ni >> 1, hf = ni & 1;
                    const uint32_t b0h = wh[nj][hf], b1h = wh[nj][hf + 2];
                    const uint32_t b0l = wl[nj][hf], b1l = wl[nj][hf + 2];
                    mma16816(acc[mi][ni], ah[mi], b0h, b1h);   // hi*hi
                    mma16816(acc[mi][ni], al[mi], b0h, b1h);   // lo*hi
                    mma16816(acc[mi][ni], ah[mi], b0l, b1l);   // hi*lo
                }
        }
        __syncthreads();
    }

    // ---- epilogue ----
    float2 bv[4];
#pragma unroll
    for (int ni = 0; ni < 4; ++ni) {
        const int n = n0 + wn + ni * 8 + (lane & 3) * 2;
        bv[ni] = *(const float2*)&bias[n];
    }
#pragma unroll
    for (int mi = 0; mi < 4; ++mi) {
        const int m = m0 + wm + mi * 16 + (lane >> 2);
#pragma unroll
        for (int ni = 0; ni < 4; ++ni) {
            const int n = n0 + wn + ni * 8 + (lane & 3) * 2;
            if (m < M) {
                float2 o = make_float2(acc[mi][ni][0] + bv[ni].x, acc[mi][ni][1] + bv[ni].y);
                *(float2*)&C[(size_t)m * DIM_ + n] = o;
            }
            if (m + 8 < M) {
                float2 o = make_float2(acc[mi][ni][2] + bv[ni].x, acc[mi][ni][3] + bv[ni].y);
                *(float2*)&C[(size_t)(m + 8) * DIM_ + n] = o;
            }
        }
    }
}

// ============================================================================
// Cache window copy: window tokens [0, NEW0) from cache, into head-major K/V
// ============================================================================
__global__ void cache_copy_kernel(const float* __restrict__ ck, const float* __restrict__ cv,
                                  float* __restrict__ Kw, float* __restrict__ Vw)
{
    int t = blockIdx.x;                 // 0..2511
    int e = threadIdx.x << 2;           // 384 threads * 4 = 1536
    int n = e >> 7, d = e & 127;
    *(float4*)&Kw[((size_t)n * KV + t) * HD + d] = *(const float4*)&ck[(size_t)(WIN0 + t) * DIM_ + e];
    *(float4*)&Vw[((size_t)n * KV + t) * HD + d] = *(const float4*)&cv[(size_t)(WIN0 + t) * DIM_ + e];
}

// ============================================================================
// RMSNorm(1536) + RoPE + scatter: Qh (head-major), K window, V window
// ============================================================================
__global__ void __launch_bounds__(256) norm_rope_kernel(
    const float* __restrict__ yq, const float* __restrict__ yk, const float* __restrict__ yv,
    const float* __restrict__ theta, const float* __restrict__ gq, const float* __restrict__ gk,
    float* __restrict__ Qh, float* __restrict__ Kw, float* __restrict__ Vw)
{
    const int s = blockIdx.x;
    const int tid = threadIdx.x;
    __shared__ float cs[64], sn[64];
    __shared__ float redq[8], redk[8];

    const int f   = s / 1560;           // frame_seqlen = 30*52
    const int rem = s % 1560;
    const int h   = rem / 52;
    const int w   = rem % 52;

    if (tid < 64) {
        int j = tid;
        int row = (j < 22) ? (5 + f) : ((j < 43) ? h : w);
        float ang = theta[row * 64 + j];
        float sv, cv; sincosf(ang, &sv, &cv);
        cs[j] = cv; sn[j] = sv;
    }

    const float* q = yq + (size_t)s * DIM_;
    const float* k = yk + (size_t)s * DIM_;
    const float* v = yv + (size_t)s * DIM_;

    float sq = 0.f, sk = 0.f;
    for (int e = tid; e < DIM_; e += 256) {
        float a = q[e]; sq += a * a;
        float b = k[e]; sk += b * b;
    }
#pragma unroll
    for (int off = 16; off; off >>= 1) {
        sq += __shfl_xor_sync(0xffffffffu, sq, off);
        sk += __shfl_xor_sync(0xffffffffu, sk, off);
    }
    if ((tid & 31) == 0) { redq[tid >> 5] = sq; redk[tid >> 5] = sk; }
    __syncthreads();
    float tq = 0.f, tk = 0.f;
#pragma unroll
    for (int i = 0; i < 8; ++i) { tq += redq[i]; tk += redk[i]; }
    const float rq = rsqrtf(tq * (1.f / 1536.f) + 1e-6f);
    const float rk = rsqrtf(tk * (1.f / 1536.f) + 1e-6f);

    for (int p = tid; p < 768; p += 256) {
        int n = p >> 6, j = p & 63;
        float c = cs[j], si = sn[j];
        int e = p << 1;
        float xr = q[e]     * rq * gq[e];
        float xi = q[e + 1] * rq * gq[e + 1];
        float* qo = Qh + ((size_t)n * S_TOK + s) * HD + (j << 1);
        qo[0] = xr * c - xi * si;
        qo[1] = xr * si + xi * c;
        float kr = k[e]     * rk * gk[e];
        float ki = k[e + 1] * rk * gk[e + 1];
        float* ko = Kw + ((size_t)n * KV + NEW0 + s) * HD + (j << 1);
        ko[0] = kr * c - ki * si;
        ko[1] = kr * si + ki * c;
    }
    for (int e = tid; e < DIM_; e += 256) {
        int n = e >> 7, d = e & 127;
        Vw[((size_t)n * KV + NEW0 + s) * HD + d] = v[e];
    }
}

// ============================================================================
// Flash attention, fp32 FFMA2. Block = (64-query tile, head). 256 threads.
// ============================================================================
#define ATTN_SMEM ((8192 + 8192 + 8192 + 4096) * 4)

__global__ void __launch_bounds__(256) attn_kernel(
    const float* __restrict__ Qh, const float* __restrict__ Kw,
    const float* __restrict__ Vw, float* __restrict__ O)
{
    extern __shared__ __align__(16) float sm[];
    float* Qs = sm;                 // 8192 floats
    float* Ks = sm + 8192;          // 8192
    float* Vs = sm + 16384;         // 8192
    float* Ps = sm + 24576;         // 4096

    const int tid  = threadIdx.x;
    const int head = blockIdx.y;
    const int m0   = blockIdx.x * 64;
    const int ty   = tid >> 4, tx = tid & 15;
    const float scale = 0.08838834764831845f;  // 1/sqrt(128)

#pragma unroll
    for (int p = 0; p < 8; ++p) {
        int fidx = tid + p * 256;
        int r  = fidx >> 5;
        int dq = (fidx & 31) << 2;
        float4 v = make_float4(0.f, 0.f, 0.f, 0.f);
        int sg = m0 + r;
        if (sg < S_TOK) v = *(const float4*)&Qh[((size_t)head * S_TOK + sg) * HD + dq];
        int co = (((r >> 2) ^ ((dq >> 2) & 15)) << 2) + (r & 3);
        Qs[(dq + 0) * 64 + co] = v.x * scale;
        Qs[(dq + 1) * 64 + co] = v.y * scale;
        Qs[(dq + 2) * 64 + co] = v.z * scale;
        Qs[(dq + 3) * 64 + co] = v.w * scale;
    }

    u64 o2[4][4];
#pragma unroll
    for (int i = 0; i < 4; ++i)
#pragma unroll
        for (int j = 0; j < 4; ++j) o2[i][j] = 0ull;
    float mrow[4] = {-1e30f, -1e30f, -1e30f, -1e30f};
    float lrow[4] = {0.f, 0.f, 0.f, 0.f};

    for (int kt = 0; kt < NKT; ++kt) {
        const int t0 = kt * 64;
        __syncthreads();
#pragma unroll
        for (int p = 0; p < 8; ++p) {
            int fidx = tid + p * 256;
            int c  = fidx >> 5;
            int dd = (fidx & 31) << 2;
            const float4 kvv = *(const float4*)&Kw[((size_t)head * KV + t0 + c) * HD + dd];
            int co = (((c >> 2) ^ ((dd >> 2) & 15)) << 2) + (c & 3);
            Ks[(dd + 0) * 64 + co] = kvv.x;
            Ks[(dd + 1) * 64 + co] = kvv.y;
            Ks[(dd + 2) * 64 + co] = kvv.z;
            Ks[(dd + 3) * 64 + co] = kvv.w;
            *(float4*)&Vs[c * HD + dd] = *(const float4*)&Vw[((size_t)head * KV + t0 + c) * HD + dd];
        }
        __syncthreads();

        u64 s2[4][2];
#pragma unroll
        for (int i = 0; i < 4; ++i) { s2[i][0] = 0ull; s2[i][1] = 0ull; }
#pragma unroll 8
        for (int kk = 0; kk < 128; ++kk) {
            int g = (kk >> 2) & 15;
            float4 a = *(const float4*)&Qs[kk * 64 + ((ty ^ g) << 2)];
            ulonglong2 w = *(const ulonglong2*)&Ks[kk * 64 + ((tx ^ g) << 2)];
            u64 b0 = bc2(a.x), b1 = bc2(a.y), b2 = bc2(a.z), b3 = bc2(a.w);
            fma2(s2[0][0], b0, w.x); fma2(s2[0][1], b0, w.y);
            fma2(s2[1][0], b1, w.x); fma2(s2[1][1], b1, w.y);
            fma2(s2[2][0], b2, w.x); fma2(s2[2][1], b2, w.y);
            fma2(s2[3][0], b3, w.x); fma2(s2[3][1], b3, w.y);
        }

        float sc[4][4];
#pragma unroll
        for (int rr = 0; rr < 4; ++rr) {
            float2 a = up2(s2[rr][0]), b = up2(s2[rr][1]);
            sc[rr][0] = a.x; sc[rr][1] = a.y; sc[rr][2] = b.x; sc[rr][3] = b.y;
        }
#pragma unroll
        for (int rr = 0; rr < 4; ++rr) {
            float m = fmaxf(fmaxf(sc[rr][0], sc[rr][1]), fmaxf(sc[rr][2], sc[rr][3]));
#pragma unroll
            for (int off = 1; off < 16; off <<= 1)
                m = fmaxf(m, __shfl_xor_sync(0xffffffffu, m, off));
            float mn = fmaxf(mrow[rr], m);
            float alpha = __expf(mrow[rr] - mn);
            mrow[rr] = mn;
            float rs = 0.f;
#pragma unroll
            for (int j = 0; j < 4; ++j) {
                float pv = __expf(sc[rr][j] - mn);
                sc[rr][j] = pv; rs += pv;
            }
#pragma unroll
            for (int off = 1; off < 16; off <<= 1)
                rs += __shfl_xor_sync(0xffffffffu, rs, off);
            lrow[rr] = lrow[rr] * alpha + rs;
            u64 a2 = bc2(alpha);
#pragma unroll
            for (int j = 0; j < 4; ++j) mul2(o2[rr][j], a2);
        }

#pragma unroll
        for (int jj = 0; jj < 4; ++jj)
#pragma unroll
            for (int rr = 0; rr < 4; ++rr)
                Ps[((tx << 2) + jj) * 64 + ((ty ^ tx) << 2) + rr] = sc[rr][jj];
        __syncthreads();

#pragma unroll 4
        for (int kk = 0; kk < 64; ++kk) {
            int gk = (kk >> 2) & 15;
            float4 pv = *(const float4*)&Ps[kk * 64 + ((ty ^ gk) << 2)];
            ulonglong2 v0 = *(const ulonglong2*)&Vs[kk * HD + (tx << 2)];
            ulonglong2 v1 = *(const ulonglong2*)&Vs[kk * HD + 64 + (tx << 2)];
            u64 b0 = bc2(pv.x), b1 = bc2(pv.y), b2 = bc2(pv.z), b3 = bc2(pv.w);
            fma2(o2[0][0], b0, v0.x); fma2(o2[0][1], b0, v0.y);
            fma2(o2[0][2], b0, v1.x); fma2(o2[0][3], b0, v1.y);
            fma2(o2[1][0], b1, v0.x); fma2(o2[1][1], b1, v0.y);
            fma2(o2[1][2], b1, v1.x); fma2(o2[1][3], b1, v1.y);
            fma2(o2[2][0], b2, v0.x); fma2(o2[2][1], b2, v0.y);
            fma2(o2[2][2], b2, v1.x); fma2(o2[2][3], b2, v1.y);
            fma2(o2[3][0], b3, v0.x); fma2(o2[3][1], b3, v0.y);
            fma2(o2[3][2], b3, v1.x); fma2(o2[3][3], b3, v1.y);
        }
    }

#pragma unroll
    for (int rr = 0; rr < 4; ++rr) {
        int q = m0 + (ty << 2) + rr;
        if (q >= S_TOK) continue;
        float inv = 1.f / lrow[rr];
        float2 p0 = up2(o2[rr][0]), p1 = up2(o2[rr][1]);
        float2 p2 = up2(o2[rr][2]), p3 = up2(o2[rr][3]);
        float4 w0 = make_float4(p0.x * inv, p0.y * inv, p1.x * inv, p1.y * inv);
        float4 w1 = make_float4(p2.x * inv, p2.y * inv, p3.x * inv, p3.y * inv);
        float* base = O + (size_t)q * DIM_ + head * HD;
        *(float4*)&base[(tx << 2)]      = w0;
        *(float4*)&base[64 + (tx << 2)] = w1;
    }
}

// ============================================================================
extern "C" void kernel_launch(void* const* d_in, const int* in_sizes, int n_in,
                              void* d_out, int out_size)
{
    const float* x     = (const float*)d_in[0];
    const float* theta = (const float*)d_in[1];
    const float* ck    = (const float*)d_in[2];
    const float* cv    = (const float*)d_in[3];
    const float* wq    = (const float*)d_in[4];
    const float* bq    = (const float*)d_in[5];
    const float* wk    = (const float*)d_in[6];
    const float* bk    = (const float*)d_in[7];
    const float* wv    = (const float*)d_in[8];
    const float* bv    = (const float*)d_in[9];
    const float* wo    = (const float*)d_in[10];
    const float* bo    = (const float*)d_in[11];
    const float* gq    = (const float*)d_in[12];
    const float* gk    = (const float*)d_in[13];
    float* out = (float*)d_out;

    float* scr = nullptr;
    cudaGetSymbolAddress((void**)&scr, g_scratch);
    float* yq  = scr;
    float* yk  = scr + (size_t)SD;
    float* yv  = scr + 2 * (size_t)SD;
    float* Qh  = scr + 3 * (size_t)SD;
    float* Oat = scr + 4 * (size_t)SD;
    float* Kw  = scr + 5 * (size_t)SD;
    float* Vw  = Kw + KVD;

    __nv_bfloat16 *xhi, *xlo, *whi, *wlo, *ohi, *olo;
    cudaGetSymbolAddress((void**)&xhi, g_xhi);
    cudaGetSymbolAddress((void**)&xlo, g_xlo);
    cudaGetSymbolAddress((void**)&whi, g_whi);
    cudaGetSymbolAddress((void**)&wlo, g_wlo);
    cudaGetSymbolAddress((void**)&ohi, g_ohi);
    cudaGetSymbolAddress((void**)&olo, g_olo);

    cudaFuncSetAttribute(attn_kernel, cudaFuncAttributeMaxDynamicSharedMemorySize, ATTN_SMEM);
    cudaFuncSetAttribute(gemm_mma, cudaFuncAttributeMaxDynamicSharedMemorySize, GEMM_SMEM);

    const int SD4 = SD / 4, W4 = WSZ / 4;
    split_kernel<<<(SD4 + 255) / 256, 256>>>(x,  xhi, xlo, SD4);
    split_kernel<<<(W4 + 255) / 256, 256>>>(wq, whi + 0 * (size_t)WSZ, wlo + 0 * (size_t)WSZ, W4);
    split_kernel<<<(W4 + 255) / 256, 256>>>(wk, whi + 1 * (size_t)WSZ, wlo + 1 * (size_t)WSZ, W4);
    split_kernel<<<(W4 + 255) / 256, 256>>>(wv, whi + 2 * (size_t)WSZ, wlo + 2 * (size_t)WSZ, W4);
    split_kernel<<<(W4 + 255) / 256, 256>>>(wo, whi + 3 * (size_t)WSZ, wlo + 3 * (size_t)WSZ, W4);

    dim3 gg(12, 25);   // N=1536/128, M=ceil(3120/128)
    gemm_mma<<<gg, 256, GEMM_SMEM>>>(xhi, xlo, whi + 0 * (size_t)WSZ, wlo + 0 * (size_t)WSZ, bq, yq, S_TOK);
    gemm_mma<<<gg, 256, GEMM_SMEM>>>(xhi, xlo, whi + 1 * (size_t)WSZ, wlo + 1 * (size_t)WSZ, bk, yk, S_TOK);
    gemm_mma<<<gg, 256, GEMM_SMEM>>>(xhi, xlo, whi + 2 * (size_t)WSZ, wlo + 2 * (size_t)WSZ, bv, yv, S_TOK);

    cache_copy_kernel<<<NEW0, 384>>>(ck, cv, Kw, Vw);
    norm_rope_kernel<<<S_TOK, 256>>>(yq, yk, yv, theta, gq, gk, Qh, Kw, Vw);
    attn_kernel<<<dim3(49, NH), 256, ATTN_SMEM>>>(Qh, Kw, Vw, Oat);

    split_kernel<<<(SD4 + 255) / 256, 256>>>(Oat, ohi, olo, SD4);
    gemm_mma<<<gg, 256, GEMM_SMEM>>>(ohi, olo, whi + 3 * (size_t)WSZ, wlo + 3 * (size_t)WSZ, bo, out, S_TOK);
}

// round 12
// speedup vs baseline: 2.8816x; 2.3667x over previous
#include <cuda_runtime.h>
#include <cuda_bf16.h>
#include <cstdint>

typedef unsigned long long u64;

// ---------------- problem constants (fixed by setup_inputs) ----------------
#define S_TOK 3120          // F*H*W = 2*30*52
#define DIM_  1536
#define NH    12
#define HD    128
#define KV    5632          // attention window length (== MAX_ATTN exactly)
#define NKT   88            // KV / 64
#define NEW0  2512          // offset of new tokens inside window (7800-5288)
#define WIN0  5288          // window start in cache
#define SD    (S_TOK*DIM_)              // 4,792,320
#define KVD   ((size_t)NH*KV*HD)        // 8,650,752
#define WSZ   (DIM_*DIM_)               // 2,359,296
#define QSCALE 0.08838834764831845f     // 1/sqrt(128)

// fp32 scratch: yq | yk | yv | Oattn(token-major)
__device__ float g_scratch[4*(size_t)SD];
// split-bf16 scratch (GEMM operands)
__device__ __align__(16) __nv_bfloat16 g_xhi[SD], g_xlo[SD];
__device__ __align__(16) __nv_bfloat16 g_whi[4*(size_t)WSZ], g_wlo[4*(size_t)WSZ];
__device__ __align__(16) __nv_bfloat16 g_ohi[SD], g_olo[SD];
// split-bf16 attention operands (head-major)
__device__ __align__(16) __nv_bfloat16 g_qh[SD], g_ql[SD];
__device__ __align__(16) __nv_bfloat16 g_kh[KVD], g_kl[KVD];
__device__ __align__(16) __nv_bfloat16 g_vh[KVD], g_vl[KVD];

// ---------------- mma.sync / ldmatrix / cp.async helpers (NOT a-gated) ------
__device__ __forceinline__ uint32_t smem_u32(const void* p) {
    uint32_t a; asm("{ .reg .u64 t; cvta.to.shared.u64 t, %1; cvt.u32.u64 %0, t; }" : "=r"(a) : "l"(p));
    return a;
}
__device__ __forceinline__ void ldsm4(uint32_t* r, uint32_t a) {
    asm volatile("ldmatrix.sync.aligned.m8n8.x4.shared.b16 {%0,%1,%2,%3}, [%4];"
                 : "=r"(r[0]), "=r"(r[1]), "=r"(r[2]), "=r"(r[3]) : "r"(a));
}
__device__ __forceinline__ void ldsm4t(uint32_t* r, uint32_t a) {
    asm volatile("ldmatrix.sync.aligned.m8n8.x4.trans.shared.b16 {%0,%1,%2,%3}, [%4];"
                 : "=r"(r[0]), "=r"(r[1]), "=r"(r[2]), "=r"(r[3]) : "r"(a));
}
__device__ __forceinline__ void mma16816(float* c, const uint32_t* a, uint32_t b0, uint32_t b1) {
    asm volatile("mma.sync.aligned.m16n8k16.row.col.f32.bf16.bf16.f32 "
                 "{%0,%1,%2,%3}, {%4,%5,%6,%7}, {%8,%9}, {%0,%1,%2,%3};"
                 : "+f"(c[0]), "+f"(c[1]), "+f"(c[2]), "+f"(c[3])
                 : "r"(a[0]), "r"(a[1]), "r"(a[2]), "r"(a[3]), "r"(b0), "r"(b1));
}
__device__ __forceinline__ void cp16(uint32_t d, const void* s) {
    asm volatile("cp.async.cg.shared.global [%0], [%1], 16;" :: "r"(d), "l"(s));
}
__device__ __forceinline__ void cp16z(uint32_t d, const void* s, int sz) {
    asm volatile("cp.async.cg.shared.global [%0], [%1], 16, %2;" :: "r"(d), "l"(s), "r"(sz));
}
__device__ __forceinline__ void cp_commit() {
    asm volatile("cp.async.commit_group;" ::: "memory");
}
template<int N> __device__ __forceinline__ void cp_wait() {
    asm volatile("cp.async.wait_group %0;" :: "n"(N) : "memory");
}
__device__ __forceinline__ uint32_t sw128(uint32_t off) { return off ^ ((off >> 3) & 0x70); }

// pack two fp32 into bf16x2 hi + residual lo (lo slot = first elem)
__device__ __forceinline__ void packsplit(float x, float y, uint32_t& hi, uint32_t& lo) {
    uint32_t h; asm("cvt.rn.bf16x2.f32 %0, %1, %2;" : "=r"(h) : "f"(y), "f"(x));
    float hx = __uint_as_float(h << 16);
    float hy = __uint_as_float(h & 0xffff0000u);
    uint32_t l; asm("cvt.rn.bf16x2.f32 %0, %1, %2;" : "=r"(l) : "f"(y - hy), "f"(x - hx));
    hi = h; lo = l;
}

// ============================================================================
// split fp32 -> (hi, lo) bf16 pair. n4 = elems/4.
// ============================================================================
__global__ void __launch_bounds__(256) split_kernel(
    const float* __restrict__ src, __nv_bfloat16* __restrict__ hi,
    __nv_bfloat16* __restrict__ lo, int n4)
{
    int i = blockIdx.x * 256 + threadIdx.x;
    if (i >= n4) return;
    float4 v = ((const float4*)src)[i];
    uint32_t h0, l0, h1, l1;
    packsplit(v.x, v.y, h0, l0);
    packsplit(v.z, v.w, h1, l1);
    ((uint2*)hi)[i] = make_uint2(h0, h1);
    ((uint2*)lo)[i] = make_uint2(l0, l1);
}

// ============================================================================
// Split-bf16 GEMM (NT) via mma.sync.m16n8k16 (validated in R10)
// ============================================================================
#define T_AH 0
#define T_AL 16384
#define T_WH 32768
#define T_WL 49152
#define STAGE_B 65536
#define GEMM_SMEM (2*STAGE_B)

__global__ void __launch_bounds__(256) gemm_mma(
    const __nv_bfloat16* __restrict__ Ah, const __nv_bfloat16* __restrict__ Al,
    const __nv_bfloat16* __restrict__ Wh, const __nv_bfloat16* __restrict__ Wl,
    const float* __restrict__ bias, float* __restrict__ C, int M)
{
    extern __shared__ __align__(16) char smem[];
    const uint32_t sb = smem_u32(smem);
    const int tid  = threadIdx.x;
    const int lane = tid & 31;
    const int warp = tid >> 5;
    const int m0 = blockIdx.y * 128, n0 = blockIdx.x * 128;
    const int wm = (warp >> 2) * 64;
    const int wn = (warp & 3) * 32;
    const int lrow = tid >> 3;
    const int lch  = tid & 7;

    float acc[4][4][4];
#pragma unroll
    for (int mi = 0; mi < 4; ++mi)
#pragma unroll
        for (int ni = 0; ni < 4; ++ni)
#pragma unroll
            for (int j = 0; j < 4; ++j) acc[mi][ni][j] = 0.f;

    auto load_stage = [&](int c, int buf) {
        const uint32_t db = sb + buf * STAGE_B;
        const int kc = c * 64 + lch * 8;
#pragma unroll
        for (int i = 0; i < 4; ++i) {
            const int row = lrow + 32 * i;
            const uint32_t so = sw128((uint32_t)(row * 128 + lch * 16));
            const int mg = m0 + row;
            const int sz = (mg < M) ? 16 : 0;
            const size_t ao = (size_t)mg * DIM_ + kc;
            cp16z(db + T_AH + so, Ah + ao, sz);
            cp16z(db + T_AL + so, Al + ao, sz);
            const size_t wo = (size_t)(n0 + row) * DIM_ + kc;
            cp16(db + T_WH + so, Wh + wo);
            cp16(db + T_WL + so, Wl + wo);
        }
    };

    load_stage(0, 0);
    cp_commit();

    for (int c = 0; c < 24; ++c) {
        if (c < 23) { load_stage(c + 1, (c + 1) & 1); cp_commit(); }
        if (c < 23) cp_wait<1>(); else cp_wait<0>();
        __syncthreads();

        const uint32_t base = sb + (c & 1) * STAGE_B;
        const int rA = wm + (lane & 15);
        const int rW = wn + (lane & 15);
#pragma unroll
        for (int ks = 0; ks < 4; ++ks) {
            const int kb = ks * 32 + ((lane >> 4) << 4);
            uint32_t ah[4][4], al[4][4], wh[2][4], wl[2][4];
#pragma unroll
            for (int mi = 0; mi < 4; ++mi) {
                ldsm4(ah[mi], base + T_AH + sw128((uint32_t)((rA + mi * 16) * 128 + kb)));
                ldsm4(al[mi], base + T_AL + sw128((uint32_t)((rA + mi * 16) * 128 + kb)));
            }
#pragma unroll
            for (int nj = 0; nj < 2; ++nj) {
                ldsm4(wh[nj], base + T_WH + sw128((uint32_t)((rW + nj * 16) * 128 + kb)));
                ldsm4(wl[nj], base + T_WL + sw128((uint32_t)((rW + nj * 16) * 128 + kb)));
            }
#pragma unroll
            for (int mi = 0; mi < 4; ++mi)
#pragma unroll
                for (int ni = 0; ni < 4; ++ni) {
                    const int nj = ni >> 1, hf = ni & 1;
                    const uint32_t b0h = wh[nj][hf], b1h = wh[nj][hf + 2];
                    const uint32_t b0l = wl[nj][hf], b1l = wl[nj][hf + 2];
                    mma16816(acc[mi][ni], ah[mi], b0h, b1h);
                    mma16816(acc[mi][ni], al[mi], b0h, b1h);
                    mma16816(acc[mi][ni], ah[mi], b0l, b1l);
                }
        }
        __syncthreads();
    }

    float2 bv[4];
#pragma unroll
    for (int ni = 0; ni < 4; ++ni) {
        const int n = n0 + wn + ni * 8 + (lane & 3) * 2;
        bv[ni] = *(const float2*)&bias[n];
    }
#pragma unroll
    for (int mi = 0; mi < 4; ++mi) {
        const int m = m0 + wm + mi * 16 + (lane >> 2);
#pragma unroll
        for (int ni = 0; ni < 4; ++ni) {
            const int n = n0 + wn + ni * 8 + (lane & 3) * 2;
            if (m < M) {
                float2 o = make_float2(acc[mi][ni][0] + bv[ni].x, acc[mi][ni][1] + bv[ni].y);
                *(float2*)&C[(size_t)m * DIM_ + n] = o;
            }
            if (m + 8 < M) {
                float2 o = make_float2(acc[mi][ni][2] + bv[ni].x, acc[mi][ni][3] + bv[ni].y);
                *(float2*)&C[(size_t)(m + 8) * DIM_ + n] = o;
            }
        }
    }
}

// ============================================================================
// Cache window copy -> split bf16 head-major K/V  (tokens [0, NEW0))
// ============================================================================
__global__ void cache_copy_kernel(const float* __restrict__ ck, const float* __restrict__ cv,
                                  __nv_bfloat16* __restrict__ Kh, __nv_bfloat16* __restrict__ Kl,
                                  __nv_bfloat16* __restrict__ Vh, __nv_bfloat16* __restrict__ Vl)
{
    int t = blockIdx.x;                 // 0..2511
    int e = threadIdx.x << 2;           // 384 threads * 4 = 1536
    int n = e >> 7, d = e & 127;
    size_t dst = ((size_t)n * KV + t) * HD + d;
    float4 kv = *(const float4*)&ck[(size_t)(WIN0 + t) * DIM_ + e];
    float4 vv = *(const float4*)&cv[(size_t)(WIN0 + t) * DIM_ + e];
    uint32_t h0, l0, h1, l1;
    packsplit(kv.x, kv.y, h0, l0); packsplit(kv.z, kv.w, h1, l1);
    *(uint2*)&Kh[dst] = make_uint2(h0, h1);
    *(uint2*)&Kl[dst] = make_uint2(l0, l1);
    packsplit(vv.x, vv.y, h0, l0); packsplit(vv.z, vv.w, h1, l1);
    *(uint2*)&Vh[dst] = make_uint2(h0, h1);
    *(uint2*)&Vl[dst] = make_uint2(l0, l1);
}

// ============================================================================
// RMSNorm(1536) + RoPE -> split-bf16 head-major Q, K(@NEW0), V(@NEW0)
// Q gets attention scale folded in.
// ============================================================================
__global__ void __launch_bounds__(256) norm_rope_kernel(
    const float* __restrict__ yq, const float* __restrict__ yk, const float* __restrict__ yv,
    const float* __restrict__ theta, const float* __restrict__ gq, const float* __restrict__ gk,
    __nv_bfloat16* __restrict__ Qh, __nv_bfloat16* __restrict__ Ql,
    __nv_bfloat16* __restrict__ Kh, __nv_bfloat16* __restrict__ Kl,
    __nv_bfloat16* __restrict__ Vh, __nv_bfloat16* __restrict__ Vl)
{
    const int s = blockIdx.x;
    const int tid = threadIdx.x;
    __shared__ float cs[64], sn[64];
    __shared__ float redq[8], redk[8];

    const int f   = s / 1560;           // frame_seqlen = 30*52
    const int rem = s % 1560;
    const int h   = rem / 52;
    const int w   = rem % 52;

    if (tid < 64) {
        int j = tid;
        int row = (j < 22) ? (5 + f) : ((j < 43) ? h : w);
        float ang = theta[row * 64 + j];
        float sv, cv; sincosf(ang, &sv, &cv);
        cs[j] = cv; sn[j] = sv;
    }

    const float* q = yq + (size_t)s * DIM_;
    const float* k = yk + (size_t)s * DIM_;
    const float* v = yv + (size_t)s * DIM_;

    float sq = 0.f, sk = 0.f;
    for (int e = tid; e < DIM_; e += 256) {
        float a = q[e]; sq += a * a;
        float b = k[e]; sk += b * b;
    }
#pragma unroll
    for (int off = 16; off; off >>= 1) {
        sq += __shfl_xor_sync(0xffffffffu, sq, off);
        sk += __shfl_xor_sync(0xffffffffu, sk, off);
    }
    if ((tid & 31) == 0) { redq[tid >> 5] = sq; redk[tid >> 5] = sk; }
    __syncthreads();
    float tq = 0.f, tk = 0.f;
#pragma unroll
    for (int i = 0; i < 8; ++i) { tq += redq[i]; tk += redk[i]; }
    const float rq = rsqrtf(tq * (1.f / 1536.f) + 1e-6f);
    const float rk = rsqrtf(tk * (1.f / 1536.f) + 1e-6f);

    for (int p = tid; p < 768; p += 256) {
        int n = p >> 6, j = p & 63;
        float c = cs[j], si = sn[j];
        int e = p << 1;
        // Q (scale folded)
        float xr = q[e]     * rq * gq[e];
        float xi = q[e + 1] * rq * gq[e + 1];
        float qr = (xr * c - xi * si) * QSCALE;
        float qi = (xr * si + xi * c) * QSCALE;
        size_t qo = ((size_t)n * S_TOK + s) * HD + (j << 1);
        uint32_t hi, lo;
        packsplit(qr, qi, hi, lo);
        *(uint32_t*)&Qh[qo] = hi; *(uint32_t*)&Ql[qo] = lo;
        // K
        float kr0 = k[e]     * rk * gk[e];
        float ki0 = k[e + 1] * rk * gk[e + 1];
        float kr = kr0 * c - ki0 * si;
        float ki = kr0 * si + ki0 * c;
        size_t ko = ((size_t)n * KV + NEW0 + s) * HD + (j << 1);
        packsplit(kr, ki, hi, lo);
        *(uint32_t*)&Kh[ko] = hi; *(uint32_t*)&Kl[ko] = lo;
        // V
        float v0 = v[e], v1 = v[e + 1];
        packsplit(v0, v1, hi, lo);
        *(uint32_t*)&Vh[ko] = hi; *(uint32_t*)&Vl[ko] = lo;
    }
}

// ============================================================================
// Flash attention via mma.sync split-bf16 (FA2-style, Q in registers).
// Block: 128 queries x 1 head, 256 threads (8 warps x 16 q-rows).
// smem: 2 stages x (Kh|Kl|Vh|Vl), each 64x128 bf16 (16KB) = 64KB/stage.
// Swizzle: 256B rows, 16B chunk index XOR (row&7).
// ============================================================================
#define AT_SMEM (2*65536)

__global__ void __launch_bounds__(256, 1) attn_mma(
    const __nv_bfloat16* __restrict__ Qh_, const __nv_bfloat16* __restrict__ Ql_,
    const __nv_bfloat16* __restrict__ Kh_, const __nv_bfloat16* __restrict__ Kl_,
    const __nv_bfloat16* __restrict__ Vh_, const __nv_bfloat16* __restrict__ Vl_,
    float* __restrict__ O)
{
    extern __shared__ __align__(16) char smem[];
    const uint32_t sb = smem_u32(smem);
    const int tid = threadIdx.x, lane = tid & 31, warp = tid >> 5;
    const int head = blockIdx.y;
    const int q0 = blockIdx.x * 128;

    // ---- stage Q tile (hi at 0, lo at +32768), then load A-fragments ----
#pragma unroll
    for (int i = 0; i < 8; ++i) {
        int slot = tid + i * 256;          // 0..2047
        int row = slot >> 4, ch = slot & 15;
        int qg = q0 + row;
        int sz = (qg < S_TOK) ? 16 : 0;
        if (qg >= S_TOK) qg = S_TOK - 1;   // keep src in-bounds
        const size_t off = ((size_t)head * S_TOK + qg) * HD + ch * 8;
        uint32_t d = sb + (row << 8) + (((uint32_t)(ch ^ (row & 7))) << 4);
        cp16z(d, Qh_ + off, sz);
        cp16z(d + 32768, Ql_ + off, sz);
    }
    cp_commit(); cp_wait<0>(); __syncthreads();

    uint32_t qh[8][4], ql[8][4];
    {
        const int row = warp * 16 + (lane & 15);
#pragma unroll
        for (int kc = 0; kc < 8; ++kc) {
            int ch = 2 * kc + ((lane >> 4) & 1);
            uint32_t a = sb + (row << 8) + (((uint32_t)(ch ^ (row & 7))) << 4);
            ldsm4(qh[kc], a);
            ldsm4(ql[kc], a + 32768);
        }
    }
    __syncthreads();    // Q in regs; smem free for KV stages

    float oacc[16][4];
#pragma unroll
    for (int i = 0; i < 16; ++i)
#pragma unroll
        for (int j = 0; j < 4; ++j) oacc[i][j] = 0.f;
    float mr0 = -1e30f, mr1 = -1e30f, lr0 = 0.f, lr1 = 0.f;

    auto load_kv = [&](int kt, int buf) {
        const uint32_t db = sb + buf * 65536;
        const int t0 = kt * 64;
#pragma unroll
        for (int i = 0; i < 4; ++i) {
            int slot = tid + i * 256;       // 0..1023
            int row = slot >> 4, ch = slot & 15;
            const size_t off = ((size_t)head * KV + t0 + row) * HD + ch * 8;
            uint32_t d = (uint32_t)((row << 8) + ((ch ^ (row & 7)) << 4));
            cp16(db + d,         Kh_ + off);
            cp16(db + 16384 + d, Kl_ + off);
            cp16(db + 32768 + d, Vh_ + off);
            cp16(db + 49152 + d, Vl_ + off);
        }
    };

    load_kv(0, 0); cp_commit();

    for (int kt = 0; kt < NKT; ++kt) {
        if (kt < NKT - 1) { load_kv(kt + 1, (kt + 1) & 1); cp_commit(); cp_wait<1>(); }
        else cp_wait<0>();
        __syncthreads();
        const uint32_t kb = sb + (kt & 1) * 65536;

        // ---- S = Q K^T ----
        float sacc[8][4];
#pragma unroll
        for (int i = 0; i < 8; ++i)
#pragma unroll
            for (int j = 0; j < 4; ++j) sacc[i][j] = 0.f;

#pragma unroll
        for (int kc = 0; kc < 8; ++kc) {
#pragma unroll
            for (int ng = 0; ng < 4; ++ng) {
                const int key = 16 * ng + (lane & 15);
                const int ch = 2 * kc + ((lane >> 4) & 1);
                uint32_t a = kb + (key << 8) + (((uint32_t)(ch ^ (key & 7))) << 4);
                uint32_t khf[4], klf[4];
                ldsm4(khf, a);
                ldsm4(klf, a + 16384);
                mma16816(sacc[2 * ng],     qh[kc], khf[0], khf[2]);
                mma16816(sacc[2 * ng],     ql[kc], khf[0], khf[2]);
                mma16816(sacc[2 * ng],     qh[kc], klf[0], klf[2]);
                mma16816(sacc[2 * ng + 1], qh[kc], khf[1], khf[3]);
                mma16816(sacc[2 * ng + 1], ql[kc], khf[1], khf[3]);
                mma16816(sacc[2 * ng + 1], qh[kc], klf[1], klf[3]);
            }
        }

        // ---- online softmax in fragments (rows r0=lane>>2, r1=r0+8) ----
        float tm0 = -1e30f, tm1 = -1e30f;
#pragma unroll
        for (int i = 0; i < 8; ++i) {
            tm0 = fmaxf(tm0, fmaxf(sacc[i][0], sacc[i][1]));
            tm1 = fmaxf(tm1, fmaxf(sacc[i][2], sacc[i][3]));
        }
        tm0 = fmaxf(tm0, __shfl_xor_sync(0xffffffffu, tm0, 1));
        tm0 = fmaxf(tm0, __shfl_xor_sync(0xffffffffu, tm0, 2));
        tm1 = fmaxf(tm1, __shfl_xor_sync(0xffffffffu, tm1, 1));
        tm1 = fmaxf(tm1, __shfl_xor_sync(0xffffffffu, tm1, 2));
        const float mn0 = fmaxf(mr0, tm0), mn1 = fmaxf(mr1, tm1);
        const float al0 = __expf(mr0 - mn0), al1 = __expf(mr1 - mn1);
        mr0 = mn0; mr1 = mn1;

        float rs0 = 0.f, rs1 = 0.f;
#pragma unroll
        for (int i = 0; i < 8; ++i) {
            sacc[i][0] = __expf(sacc[i][0] - mn0); rs0 += sacc[i][0];
            sacc[i][1] = __expf(sacc[i][1] - mn0); rs0 += sacc[i][1];
            sacc[i][2] = __expf(sacc[i][2] - mn1); rs1 += sacc[i][2];
            sacc[i][3] = __expf(sacc[i][3] - mn1); rs1 += sacc[i][3];
        }
        rs0 += __shfl_xor_sync(0xffffffffu, rs0, 1);
        rs0 += __shfl_xor_sync(0xffffffffu, rs0, 2);
        rs1 += __shfl_xor_sync(0xffffffffu, rs1, 1);
        rs1 += __shfl_xor_sync(0xffffffffu, rs1, 2);
        lr0 = lr0 * al0 + rs0;
        lr1 = lr1 * al1 + rs1;

#pragma unroll
        for (int i = 0; i < 16; ++i) {
            oacc[i][0] *= al0; oacc[i][1] *= al0;
            oacc[i][2] *= al1; oacc[i][3] *= al1;
        }

        // ---- pack P into split-bf16 A-fragments (C-frag -> A-frag identity) ----
        uint32_t ph[4][4], pl[4][4];
#pragma unroll
        for (int kc = 0; kc < 4; ++kc) {
            packsplit(sacc[2 * kc][0],     sacc[2 * kc][1],     ph[kc][0], pl[kc][0]);
            packsplit(sacc[2 * kc][2],     sacc[2 * kc][3],     ph[kc][1], pl[kc][1]);
            packsplit(sacc[2 * kc + 1][0], sacc[2 * kc + 1][1], ph[kc][2], pl[kc][2]);
            packsplit(sacc[2 * kc + 1][2], sacc[2 * kc + 1][3], ph[kc][3], pl[kc][3]);
        }

        // ---- O += P V ----
#pragma unroll
        for (int kc = 0; kc < 4; ++kc) {
#pragma unroll
            for (int ng = 0; ng < 8; ++ng) {
                const int key = 16 * kc + (lane & 15);
                const int ch = 2 * ng + ((lane >> 4) & 1);
                uint32_t a = kb + 32768 + (key << 8) + (((uint32_t)(ch ^ (key & 7))) << 4);
                uint32_t vhf[4], vlf[4];
                ldsm4t(vhf, a);
                ldsm4t(vlf, a + 16384);
                mma16816(oacc[2 * ng],     ph[kc], vhf[0], vhf[1]);
                mma16816(oacc[2 * ng],     pl[kc], vhf[0], vhf[1]);
                mma16816(oacc[2 * ng],     ph[kc], vlf[0], vlf[1]);
                mma16816(oacc[2 * ng + 1], ph[kc], vhf[2], vhf[3]);
                mma16816(oacc[2 * ng + 1], pl[kc], vhf[2], vhf[3]);
                mma16816(oacc[2 * ng + 1], ph[kc], vlf[2], vlf[3]);
            }
        }
        __syncthreads();   // all warps done with this stage before it is refilled
    }

    // ---- epilogue: divide by l, write token-major fp32 ----
    const float inv0 = 1.f / lr0, inv1 = 1.f / lr1;
    const int r0 = warp * 16 + (lane >> 2);
    const int cn = (lane & 3) * 2;
    const int qa = q0 + r0, qb = qa + 8;
#pragma unroll
    for (int ni = 0; ni < 16; ++ni) {
        const int col = head * HD + ni * 8 + cn;
        if (qa < S_TOK)
            *(float2*)&O[(size_t)qa * DIM_ + col] = make_float2(oacc[ni][0] * inv0, oacc[ni][1] * inv0);
        if (qb < S_TOK)
            *(float2*)&O[(size_t)qb * DIM_ + col] = make_float2(oacc[ni][2] * inv1, oacc[ni][3] * inv1);
    }
}

// ============================================================================
extern "C" void kernel_launch(void* const* d_in, const int* in_sizes, int n_in,
                              void* d_out, int out_size)
{
    const float* x     = (const float*)d_in[0];
    const float* theta = (const float*)d_in[1];
    const float* ck    = (const float*)d_in[2];
    const float* cv    = (const float*)d_in[3];
    const float* wq    = (const float*)d_in[4];
    const float* bq    = (const float*)d_in[5];
    const float* wk    = (const float*)d_in[6];
    const float* bk    = (const float*)d_in[7];
    const float* wv    = (const float*)d_in[8];
    const float* bv    = (const float*)d_in[9];
    const float* wo    = (const float*)d_in[10];
    const float* bo    = (const float*)d_in[11];
    const float* gq    = (const float*)d_in[12];
    const float* gk    = (const float*)d_in[13];
    float* out = (float*)d_out;

    float* scr = nullptr;
    cudaGetSymbolAddress((void**)&scr, g_scratch);
    float* yq  = scr;
    float* yk  = scr + (size_t)SD;
    float* yv  = scr + 2 * (size_t)SD;
    float* Oat = scr + 3 * (size_t)SD;

    __nv_bfloat16 *xhi, *xlo, *whi, *wlo, *ohi, *olo;
    __nv_bfloat16 *Qh, *Ql, *Kh, *Kl, *Vh, *Vl;
    cudaGetSymbolAddress((void**)&xhi, g_xhi);
    cudaGetSymbolAddress((void**)&xlo, g_xlo);
    cudaGetSymbolAddress((void**)&whi, g_whi);
    cudaGetSymbolAddress((void**)&wlo, g_wlo);
    cudaGetSymbolAddress((void**)&ohi, g_ohi);
    cudaGetSymbolAddress((void**)&olo, g_olo);
    cudaGetSymbolAddress((void**)&Qh, g_qh);
    cudaGetSymbolAddress((void**)&Ql, g_ql);
    cudaGetSymbolAddress((void**)&Kh, g_kh);
    cudaGetSymbolAddress((void**)&Kl, g_kl);
    cudaGetSymbolAddress((void**)&Vh, g_vh);
    cudaGetSymbolAddress((void**)&Vl, g_vl);

    cudaFuncSetAttribute(gemm_mma, cudaFuncAttributeMaxDynamicSharedMemorySize, GEMM_SMEM);
    cudaFuncSetAttribute(attn_mma, cudaFuncAttributeMaxDynamicSharedMemorySize, AT_SMEM);

    const int SD4 = SD / 4, W4 = WSZ / 4;
    split_kernel<<<(SD4 + 255) / 256, 256>>>(x,  xhi, xlo, SD4);
    split_kernel<<<(W4 + 255) / 256, 256>>>(wq, whi + 0 * (size_t)WSZ, wlo + 0 * (size_t)WSZ, W4);
    split_kernel<<<(W4 + 255) / 256, 256>>>(wk, whi + 1 * (size_t)WSZ, wlo + 1 * (size_t)WSZ, W4);
    split_kernel<<<(W4 + 255) / 256, 256>>>(wv, whi + 2 * (size_t)WSZ, wlo + 2 * (size_t)WSZ, W4);
    split_kernel<<<(W4 + 255) / 256, 256>>>(wo, whi + 3 * (size_t)WSZ, wlo + 3 * (size_t)WSZ, W4);

    dim3 gg(12, 25);   // N=1536/128, M=ceil(3120/128)
    gemm_mma<<<gg, 256, GEMM_SMEM>>>(xhi, xlo, whi + 0 * (size_t)WSZ, wlo + 0 * (size_t)WSZ, bq, yq, S_TOK);
    gemm_mma<<<gg, 256, GEMM_SMEM>>>(xhi, xlo, whi + 1 * (size_t)WSZ, wlo + 1 * (size_t)WSZ, bk, yk, S_TOK);
    gemm_mma<<<gg, 256, GEMM_SMEM>>>(xhi, xlo, whi + 2 * (size_t)WSZ, wlo + 2 * (size_t)WSZ, bv, yv, S_TOK);

    cache_copy_kernel<<<NEW0, 384>>>(ck, cv, Kh, Kl, Vh, Vl);
    norm_rope_kernel<<<S_TOK, 256>>>(yq, yk, yv, theta, gq, gk, Qh, Ql, Kh, Kl, Vh, Vl);

    attn_mma<<<dim3(25, NH), 256, AT_SMEM>>>(Qh, Ql, Kh, Kl, Vh, Vl, Oat);

    split_kernel<<<(SD4 + 255) / 256, 256>>>(Oat, ohi, olo, SD4);
    gemm_mma<<<gg, 256, GEMM_SMEM>>>(ohi, olo, whi + 3 * (size_t)WSZ, wlo + 3 * (size_t)WSZ, bo, out, S_TOK);
}